// round 14
// baseline (speedup 1.0000x reference)
#include <cuda_runtime.h>
#include <math.h>
#include <stdint.h>

#define SDIM 256
#define RDIM 8192
#define BDIM 8192
#define BM 64
#define KC 32
#define NCHUNK (RDIM / KC)     // 256
#define THREADS 512
#define STAGES 3

// ---- dynamic smem layout (bytes) ----
#define A_STAGE 8192                        // 64 x 32 tf32, fragment order
#define OFF_SA 0
#define B_ROW_W 36                          // 32 data words + 4 pad
#define B_STAGE (SDIM * B_ROW_W * 4)        // 36864
#define OFF_SB (STAGES * A_STAGE)           // 24576
#define OFF_AB (OFF_SB + STAGES * B_STAGE)  // 135168
#define AB_STRIDE 257
#define OFF_MB (OFF_AB + BM * AB_STRIDE * 4)  // 200960
#define SMEM_BYTES (OFF_MB + 2 * STAGES * 8)  // 201008
// mbarriers: full[s] (A ready) @ OFF_MB + s*8 ; empty[s] @ OFF_MB + 24 + s*8

__device__ __forceinline__ uint32_t smem_u32(const void* p) {
    uint32_t a;
    asm("{ .reg .u64 t; cvta.to.shared.u64 t, %1; cvt.u32.u64 %0, t; }" : "=r"(a) : "l"(p));
    return a;
}
__device__ __forceinline__ uint32_t to_tf32(float f) {
    uint32_t u;
    asm("cvt.rna.tf32.f32 %0, %1;" : "=r"(u) : "f"(f));
    return u;
}
__device__ __forceinline__ void sts128(uint32_t a, uint32_t x, uint32_t y, uint32_t z, uint32_t w) {
    asm volatile("st.shared.v4.b32 [%0], {%1,%2,%3,%4};" :: "r"(a), "r"(x), "r"(y), "r"(z), "r"(w) : "memory");
}
__device__ __forceinline__ void lds128(uint32_t a, uint32_t* r) {
    asm volatile("ld.shared.v4.b32 {%0,%1,%2,%3}, [%4];"
                 : "=r"(r[0]), "=r"(r[1]), "=r"(r[2]), "=r"(r[3]) : "r"(a));
}
__device__ __forceinline__ uint32_t lds32(uint32_t a) {
    uint32_t r;
    asm volatile("ld.shared.b32 %0, [%1];" : "=r"(r) : "r"(a));
    return r;
}
__device__ __forceinline__ void cp16(uint32_t s, const void* g) {
    asm volatile("cp.async.cg.shared.global [%0], [%1], 16;" :: "r"(s), "l"(g));
}
#define CP_COMMIT() asm volatile("cp.async.commit_group;" ::: "memory")
#define CP_WAIT(n)  asm volatile("cp.async.wait_group %0;" :: "n"(n) : "memory")
#define BAR_CONS()  asm volatile("bar.sync 1, 256;" ::: "memory")
#define MBAR_INIT(a, n) asm volatile("mbarrier.init.shared.b64 [%0], %1;" :: "r"(a), "r"(n) : "memory")
#define MBAR_ARRIVE(a)  asm volatile("mbarrier.arrive.shared.b64 _, [%0];" :: "r"(a) : "memory")
#define MBAR_WAIT(a, par) do { \
    asm volatile("{\n\t.reg .pred P;\n\tLAB%=:\n\tmbarrier.try_wait.parity.shared.b64 P, [%0], %1, 0x989680;\n\t@!P bra LAB%=;\n\t}" \
        :: "r"(a), "r"(par) : "memory"); } while (0)

__device__ __forceinline__ void mma_tf32(float* c, const uint32_t* a, const uint32_t* b) {
    asm volatile("mma.sync.aligned.m16n8k8.row.col.f32.tf32.tf32.f32 "
                 "{%0,%1,%2,%3}, {%4,%5,%6,%7}, {%8,%9}, {%0,%1,%2,%3};"
                 : "+f"(c[0]), "+f"(c[1]), "+f"(c[2]), "+f"(c[3])
                 : "r"(a[0]), "r"(a[1]), "r"(a[2]), "r"(a[3]), "r"(b[0]), "r"(b[1]));
}

struct Prm {
    int2 m0, m1;
    float al0, al1, be0, be1, ga0, ga1;
    int rt0, rt1;
};

__global__ __launch_bounds__(THREADS, 1)
void fused_mma(const float* __restrict__ ab,
               const float* __restrict__ temperature,
               const float* __restrict__ cr_rate,
               const float* __restrict__ fuv_rate,
               const float* __restrict__ inc,
               const float* __restrict__ alpha,
               const float* __restrict__ beta,
               const float* __restrict__ gam,
               const int2*  __restrict__ rm,
               const int*   __restrict__ rtype,
               float* __restrict__ out)
{
    extern __shared__ char smem[];
    const uint32_t sb = smem_u32(smem);
    float* abT = (float*)(smem + OFF_AB);

    const int tid  = threadIdx.x;
    const int wid  = tid >> 5;
    const int lane = tid & 31;
    const int l4   = lane >> 2;      // 0..7
    const int kl   = lane & 3;       // 0..3
    const int bBase = blockIdx.x * BM;

    if (tid == 0) {
#pragma unroll
        for (int s = 0; s < STAGES; s++) {
            MBAR_INIT(sb + OFF_MB + s * 8, 256);        // full[s]: producer threads (A ready)
            MBAR_INIT(sb + OFF_MB + 24 + s * 8, 256);   // empty[s]: consumer threads
        }
    }

    // ---- abundance tile [64][257-padded] ----
#pragma unroll
    for (int i = 0; i < 8; i++) {
        int idx = tid + i * THREADS;
        int row = idx >> 6;
        int q   = idx & 63;
        float4 v = __ldg((const float4*)(ab + (size_t)(bBase + row) * SDIM) + q);
        float* dst = abT + row * AB_STRIDE + q * 4;
        dst[0] = v.x; dst[1] = v.y; dst[2] = v.z; dst[3] = v.w;
    }
    __syncthreads();   // abT + mbarriers published

    if (wid >= 8) {
        // ============ PRODUCER warps (8): A tiles only, runs ahead =========
        const int pw = wid - 8;            // 0..7
        const int ksA = pw >> 2;           // 0..1
        const int ksB = ksA + 2;           // 2..3
        const int bm  = pw & 3;            // 0..3
        const int b_base = bm * 16 + l4;

        float ltv[2], invTv[2], crv[2], fuvv[2];
#pragma unroll
        for (int j = 0; j < 2; j++) {
            int bg = bBase + b_base + 8 * j;
            float T = __ldg(temperature + bg);
            ltv[j]   = __logf(T * (1.0f / 300.0f));
            invTv[j] = 1.0f / T;
            crv[j]   = __ldg(cr_rate + bg);
            fuvv[j]  = __ldg(fuv_rate + bg);
        }

        auto load_prm = [&](int c, int ks) -> Prm {
            Prm p;
            int r0 = c * KC + ks * 8 + kl;
            int r1 = r0 + 4;
            p.m0 = __ldg(rm + r0);  p.m1 = __ldg(rm + r1);
            p.al0 = __ldg(alpha + r0); p.al1 = __ldg(alpha + r1);
            p.be0 = __ldg(beta  + r0); p.be1 = __ldg(beta  + r1);
            p.ga0 = __ldg(gam   + r0); p.ga1 = __ldg(gam   + r1);
            p.rt0 = __ldg(rtype + r0); p.rt1 = __ldg(rtype + r1);
            return p;
        };

        auto storeA = [&](const Prm& p, int g, int st) {
            float f[2][2];
#pragma unroll
            for (int j = 0; j < 2; j++) {
                const float* abRow = abT + (b_base + 8 * j) * AB_STRIDE;
                {
                    float a0 = (p.m0.x < SDIM) ? abRow[p.m0.x] : 1.0f;
                    float a1 = (p.m0.y < SDIM) ? abRow[p.m0.y] : 1.0f;
                    float x  = (p.rt0 == 0) ? fmaf(p.be0, ltv[j], -p.ga0 * invTv[j])
                                            : ((p.rt0 == 1) ? 0.0f : -p.ga0);
                    float mm = (p.rt0 == 0) ? 1.0f : ((p.rt0 == 1) ? crv[j] : fuvv[j]);
                    f[0][j] = p.al0 * __expf(x) * mm * a0 * a1;
                }
                {
                    float a0 = (p.m1.x < SDIM) ? abRow[p.m1.x] : 1.0f;
                    float a1 = (p.m1.y < SDIM) ? abRow[p.m1.y] : 1.0f;
                    float x  = (p.rt1 == 0) ? fmaf(p.be1, ltv[j], -p.ga1 * invTv[j])
                                            : ((p.rt1 == 1) ? 0.0f : -p.ga1);
                    float mm = (p.rt1 == 0) ? 1.0f : ((p.rt1 == 1) ? crv[j] : fuvv[j]);
                    f[1][j] = p.al1 * __expf(x) * mm * a0 * a1;
                }
            }
            uint32_t aB = sb + OFF_SA + st * A_STAGE;
            sts128(aB + (uint32_t)((g * 32 + lane) * 16),
                   to_tf32(f[0][0]), to_tf32(f[0][1]), to_tf32(f[1][0]), to_tf32(f[1][1]));
        };

        Prm pa = load_prm(0, ksA);
        Prm pb = load_prm(0, ksB);

        int pe = 0, peph = 1;   // empty-wait cursor (first STAGES pass free)
#pragma unroll 1
        for (int c = 0; c < NCHUNK; c++) {
            const int st = c % STAGES;
            MBAR_WAIT(sb + OFF_MB + 24 + pe * 8, peph);    // reserve A-stage
            if (++pe == STAGES) { pe = 0; peph ^= 1; }
            storeA(pa, ksA * 4 + bm, st);
            storeA(pb, ksB * 4 + bm, st);
            int cn = (c + 1 < NCHUNK) ? c + 1 : 0;
            pa = load_prm(cn, ksA);
            pb = load_prm(cn, ksB);
            MBAR_ARRIVE(sb + OFF_MB + st * 8);             // publish A(c)
        }
    } else {
        // ============ CONSUMER warps (8): B self-managed via cp.async ======
        const int wn = wid;   // 0..7 — 64x32 tile, warp-unique B

        auto cp_b = [&](int c, int st) {
            const float* src0 = inc + c * KC;
            uint32_t bB = sb + OFF_SB + st * B_STAGE;
#pragma unroll
            for (int i = 0; i < 8; i++) {
                int id = tid + i * 256;        // 0..2047
                int s = id >> 3;
                int q = id & 7;
                cp16(bB + (uint32_t)((s * B_ROW_W + q * 4) * 4),
                     src0 + (size_t)s * RDIM + q * 4);
            }
            CP_COMMIT();
        };

        float acc[4][4][4];   // [mtile][ntile][reg]
#pragma unroll
        for (int mt = 0; mt < 4; mt++)
#pragma unroll
            for (int nt = 0; nt < 4; nt++)
#pragma unroll
                for (int i = 0; i < 4; i++) acc[mt][nt][i] = 0.0f;

        // prologue: launch B(0), B(1) — two groups in flight
        cp_b(0, 0);
        cp_b(1, 1);

        int cs = 0, cph = 0;
#pragma unroll 1
        for (int c = 0; c < NCHUNK; c++) {
            MBAR_WAIT(sb + OFF_MB + cs * 8, cph);          // A(c) ready (fast path)
            if (c <= NCHUNK - 2) { CP_WAIT(1); } else { CP_WAIT(0); }  // B(c) landed
            BAR_CONS();                                    // cross-thread B visibility
            uint32_t aB = sb + OFF_SA + cs * A_STAGE;
            uint32_t bB = sb + OFF_SB + cs * B_STAGE;
#pragma unroll
            for (int ks = 0; ks < 4; ks++) {
                uint32_t bfr[4][2];
#pragma unroll
                for (int nt = 0; nt < 4; nt++) {
                    int s = wn * 32 + nt * 8 + l4;
                    uint32_t addr = bB + (uint32_t)((s * B_ROW_W + ks * 8 + kl) * 4);
                    bfr[nt][0] = lds32(addr);
                    bfr[nt][1] = lds32(addr + 16);
                }
                uint32_t afr[4][4];
#pragma unroll
                for (int mt = 0; mt < 4; mt++)
                    lds128(aB + (uint32_t)(((ks * 4 + mt) * 32 + lane) * 16), afr[mt]);
#pragma unroll
                for (int mt = 0; mt < 4; mt++)
#pragma unroll
                    for (int nt = 0; nt < 4; nt++)
                        mma_tf32(acc[mt][nt], afr[mt], bfr[nt]);
            }
            MBAR_ARRIVE(sb + OFF_MB + 24 + cs * 8);        // free A-stage
            if (c + 2 < NCHUNK)
                cp_b(c + 2, (c + 2) % STAGES);             // launch B(c+2): 2 chunks of flight
            if (++cs == STAGES) { cs = 0; cph ^= 1; }
        }

        // ---- epilogue ----
#pragma unroll
        for (int mt = 0; mt < 4; mt++) {
            int row0 = bBase + mt * 16 + l4;
#pragma unroll
            for (int nt = 0; nt < 4; nt++) {
                int col = wn * 32 + nt * 8 + 2 * kl;
                *(float2*)(out + (size_t)row0 * SDIM + col) = make_float2(acc[mt][nt][0], acc[mt][nt][1]);
                *(float2*)(out + (size_t)(row0 + 8) * SDIM + col) = make_float2(acc[mt][nt][2], acc[mt][nt][3]);
            }
        }
    }
}

extern "C" void kernel_launch(void* const* d_in, const int* in_sizes, int n_in,
                              void* d_out, int out_size) {
    const float* ab   = (const float*)d_in[1];
    const float* temp = (const float*)d_in[2];
    const float* cr   = (const float*)d_in[3];
    const float* fuv  = (const float*)d_in[4];
    const float* inc  = (const float*)d_in[5];
    const float* alp  = (const float*)d_in[6];
    const float* bet  = (const float*)d_in[7];
    const float* gam  = (const float*)d_in[8];
    const int2*  rm   = (const int2*)d_in[9];
    const int*   rty  = (const int*)d_in[10];
    float* out = (float*)d_out;

    cudaFuncSetAttribute(fused_mma, cudaFuncAttributeMaxDynamicSharedMemorySize, SMEM_BYTES);
    fused_mma<<<BDIM / BM, THREADS, SMEM_BYTES>>>(ab, temp, cr, fuv, inc, alp, bet, gam,
                                                  rm, rty, out);
}

// round 15
// speedup vs baseline: 1.0957x; 1.0957x over previous
#include <cuda_runtime.h>
#include <math.h>
#include <stdint.h>

#define SDIM 256
#define RDIM 8192
#define BDIM 8192
#define BM 64
#define KC 32
#define NCHUNK (RDIM / KC)     // 256
#define THREADS 512
#define STAGES 3

#define SCALE_F 4294967296.0f        // 2^32
#define INV_SCALE_F 2.3283064365386963e-10f  // 2^-32

// ---- dynamic smem layout (bytes) ----
#define A_STAGE 4096                        // 8 frag-groups x 32 lanes x 16B (fp16)
#define OFF_SA 0
#define B_ROW_W 36                          // 32 fp32 words + 4 pad
#define B_STAGE (SDIM * B_ROW_W * 4)        // 36864
#define OFF_SB (STAGES * A_STAGE)           // 12288
#define OFF_AB (OFF_SB + STAGES * B_STAGE)  // 122880
#define AB_STRIDE 257
#define OFF_MB (OFF_AB + BM * AB_STRIDE * 4)  // 188672
#define SMEM_BYTES (OFF_MB + 2 * STAGES * 8)  // 188720
// mbarriers: full[s] @ OFF_MB + s*8 ; empty[s] @ OFF_MB + 24 + s*8

__device__ __forceinline__ uint32_t smem_u32(const void* p) {
    uint32_t a;
    asm("{ .reg .u64 t; cvta.to.shared.u64 t, %1; cvt.u32.u64 %0, t; }" : "=r"(a) : "l"(p));
    return a;
}
__device__ __forceinline__ uint32_t pack_f16x2(float lo, float hi) {
    uint32_t r;
    asm("cvt.rn.f16x2.f32 %0, %1, %2;" : "=r"(r) : "f"(hi), "f"(lo));
    return r;
}
__device__ __forceinline__ void sts128(uint32_t a, uint32_t x, uint32_t y, uint32_t z, uint32_t w) {
    asm volatile("st.shared.v4.b32 [%0], {%1,%2,%3,%4};" :: "r"(a), "r"(x), "r"(y), "r"(z), "r"(w) : "memory");
}
__device__ __forceinline__ void lds128(uint32_t a, uint32_t* r) {
    asm volatile("ld.shared.v4.b32 {%0,%1,%2,%3}, [%4];"
                 : "=r"(r[0]), "=r"(r[1]), "=r"(r[2]), "=r"(r[3]) : "r"(a));
}
__device__ __forceinline__ void lds64f(uint32_t a, float* r) {
    asm volatile("ld.shared.v2.f32 {%0,%1}, [%2];" : "=f"(r[0]), "=f"(r[1]) : "r"(a));
}
__device__ __forceinline__ void cp16(uint32_t s, const void* g) {
    asm volatile("cp.async.cg.shared.global [%0], [%1], 16;" :: "r"(s), "l"(g));
}
#define CP_COMMIT() asm volatile("cp.async.commit_group;" ::: "memory")
#define CP_WAIT(n)  asm volatile("cp.async.wait_group %0;" :: "n"(n) : "memory")
#define MBAR_INIT(a, n) asm volatile("mbarrier.init.shared.b64 [%0], %1;" :: "r"(a), "r"(n) : "memory")
#define MBAR_ARRIVE(a)  asm volatile("mbarrier.arrive.shared.b64 _, [%0];" :: "r"(a) : "memory")
#define MBAR_WAIT(a, par) do { \
    asm volatile("{\n\t.reg .pred P;\n\tLAB%=:\n\tmbarrier.try_wait.parity.shared.b64 P, [%0], %1, 0x989680;\n\t@!P bra LAB%=;\n\t}" \
        :: "r"(a), "r"(par) : "memory"); } while (0)

__device__ __forceinline__ void mma_fp16(float* c, const uint32_t* a, const uint32_t* b) {
    asm volatile("mma.sync.aligned.m16n8k16.row.col.f32.f16.f16.f32 "
                 "{%0,%1,%2,%3}, {%4,%5,%6,%7}, {%8,%9}, {%0,%1,%2,%3};"
                 : "+f"(c[0]), "+f"(c[1]), "+f"(c[2]), "+f"(c[3])
                 : "r"(a[0]), "r"(a[1]), "r"(a[2]), "r"(a[3]), "r"(b[0]), "r"(b[1]));
}

struct Prm {
    int2 m0, m1;        // reactants for r0, r1=r0+1
    float al0, al1, be0, be1, ga0, ga1;
    int rt0, rt1;
};

__global__ __launch_bounds__(THREADS, 1)
void fused_mma(const float* __restrict__ ab,
               const float* __restrict__ temperature,
               const float* __restrict__ cr_rate,
               const float* __restrict__ fuv_rate,
               const float* __restrict__ inc,
               const float* __restrict__ alpha,
               const float* __restrict__ beta,
               const float* __restrict__ gam,
               const int2*  __restrict__ rm,
               const int*   __restrict__ rtype,
               float* __restrict__ out)
{
    extern __shared__ char smem[];
    const uint32_t sb = smem_u32(smem);
    float* abT = (float*)(smem + OFF_AB);

    const int tid  = threadIdx.x;
    const int wid  = tid >> 5;
    const int lane = tid & 31;
    const int l4   = lane >> 2;      // 0..7 (groupID)
    const int kl   = lane & 3;       // 0..3 (tid_in_group)
    const int bBase = blockIdx.x * BM;

    if (tid == 0) {
#pragma unroll
        for (int s = 0; s < STAGES; s++) {
            MBAR_INIT(sb + OFF_MB + s * 8, 256);        // full[s]: producers
            MBAR_INIT(sb + OFF_MB + 24 + s * 8, 256);   // empty[s]: consumers
        }
    }

    // ---- abundance tile [64][257-padded] ----
#pragma unroll
    for (int i = 0; i < 8; i++) {
        int idx = tid + i * THREADS;
        int row = idx >> 6;
        int q   = idx & 63;
        float4 v = __ldg((const float4*)(ab + (size_t)(bBase + row) * SDIM) + q);
        float* dst = abT + row * AB_STRIDE + q * 4;
        dst[0] = v.x; dst[1] = v.y; dst[2] = v.z; dst[3] = v.w;
    }
    __syncthreads();   // abT + mbarriers published

    if (wid >= 8) {
        // ======================= PRODUCER warps (8) =======================
        // warp = (kh 0..1) x (bm 0..3); thread covers rows b_base, b_base+8
        // and k = kh*16 + {2kl, 2kl+1, 2kl+8, 2kl+9} -> one fp16 A fragment
        const int pw = wid - 8;
        const int kh = pw >> 2;            // 0..1
        const int bm = pw & 3;             // 0..3
        const int b_base = bm * 16 + l4;
        const int tid2 = tid - 256;        // 0..255

        float ltv[2], invTv[2], crv[2], fuvv[2];
#pragma unroll
        for (int j = 0; j < 2; j++) {
            int bg = bBase + b_base + 8 * j;
            float T = __ldg(temperature + bg);
            ltv[j]   = __logf(T * (1.0f / 300.0f));
            invTv[j] = 1.0f / T;
            crv[j]   = __ldg(cr_rate + bg);
            fuvv[j]  = __ldg(fuv_rate + bg);
        }

        auto load_prm = [&](int c, int off) -> Prm {
            Prm p;
            int r0 = c * KC + kh * 16 + off + 2 * kl;
            int r1 = r0 + 1;
            p.m0 = __ldg(rm + r0);  p.m1 = __ldg(rm + r1);
            p.al0 = __ldg(alpha + r0) * SCALE_F; p.al1 = __ldg(alpha + r1) * SCALE_F;
            p.be0 = __ldg(beta  + r0); p.be1 = __ldg(beta  + r1);
            p.ga0 = __ldg(gam   + r0); p.ga1 = __ldg(gam   + r1);
            p.rt0 = __ldg(rtype + r0); p.rt1 = __ldg(rtype + r1);
            return p;
        };

        // flux for one Prm at both rows -> f[r01][row j]
        auto fluxes = [&](const Prm& p, float f[2][2]) {
#pragma unroll
            for (int j = 0; j < 2; j++) {
                const float* abRow = abT + (b_base + 8 * j) * AB_STRIDE;
                {
                    float a0 = (p.m0.x < SDIM) ? abRow[p.m0.x] : 1.0f;
                    float a1 = (p.m0.y < SDIM) ? abRow[p.m0.y] : 1.0f;
                    float x  = (p.rt0 == 0) ? fmaf(p.be0, ltv[j], -p.ga0 * invTv[j])
                                            : ((p.rt0 == 1) ? 0.0f : -p.ga0);
                    float mm = (p.rt0 == 0) ? 1.0f : ((p.rt0 == 1) ? crv[j] : fuvv[j]);
                    f[0][j] = p.al0 * __expf(x) * mm * a0 * a1;
                }
                {
                    float a0 = (p.m1.x < SDIM) ? abRow[p.m1.x] : 1.0f;
                    float a1 = (p.m1.y < SDIM) ? abRow[p.m1.y] : 1.0f;
                    float x  = (p.rt1 == 0) ? fmaf(p.be1, ltv[j], -p.ga1 * invTv[j])
                                            : ((p.rt1 == 1) ? 0.0f : -p.ga1);
                    float mm = (p.rt1 == 0) ? 1.0f : ((p.rt1 == 1) ? crv[j] : fuvv[j]);
                    f[1][j] = p.al1 * __expf(x) * mm * a0 * a1;
                }
            }
        };

        auto storeA = [&](const Prm& pa, const Prm& pb, int st) {
            float fa[2][2], fb[2][2];
            fluxes(pa, fa);     // k = 2kl, 2kl+1
            fluxes(pb, fb);     // k = 2kl+8, 2kl+9
            // m16n8k16 A frag: a0={row0,k0,k0+1} a1={row1,...} a2={row0,k0+8,...} a3={row1,...}
            uint32_t a0 = pack_f16x2(fa[0][0], fa[1][0]);
            uint32_t a1 = pack_f16x2(fa[0][1], fa[1][1]);
            uint32_t a2 = pack_f16x2(fb[0][0], fb[1][0]);
            uint32_t a3 = pack_f16x2(fb[0][1], fb[1][1]);
            uint32_t aB = sb + OFF_SA + st * A_STAGE;
            sts128(aB + (uint32_t)(((kh * 4 + bm) * 32 + lane) * 16), a0, a1, a2, a3);
        };

        auto cp_b = [&](int c, int st) {
            const float* src0 = inc + c * KC;
            uint32_t bB = sb + OFF_SB + st * B_STAGE;
#pragma unroll
            for (int i = 0; i < 8; i++) {
                int id = tid2 + i * 256;
                int s = id >> 3;
                int q = id & 7;
                cp16(bB + (uint32_t)((s * B_ROW_W + q * 4) * 4),
                     src0 + (size_t)s * RDIM + q * 4);
            }
            CP_COMMIT();
        };

        Prm pa = load_prm(0, 0);
        Prm pb = load_prm(0, 8);

        int pe = 0, peph = 1;   // empty-wait cursor
        MBAR_WAIT(sb + OFF_MB + 24 + pe * 8, peph);
        if (++pe == STAGES) { pe = 0; peph ^= 1; }
        cp_b(0, 0);

#pragma unroll 1
        for (int c = 0; c < NCHUNK; c++) {
            const int st = c % STAGES;
            storeA(pa, pb, st);
            int cn = (c + 1 < NCHUNK) ? c + 1 : 0;
            pa = load_prm(cn, 0);
            pb = load_prm(cn, 8);
            CP_WAIT(0);                         // B(c) landed
            MBAR_ARRIVE(sb + OFF_MB + st * 8);  // publish full[c]
            if (c + 1 < NCHUNK) {
                MBAR_WAIT(sb + OFF_MB + 24 + pe * 8, peph);
                if (++pe == STAGES) { pe = 0; peph ^= 1; }
                cp_b(c + 1, (c + 1) % STAGES);
            }
        }
    } else {
        // ======================= CONSUMER warps (8) =======================
        // 64x32 tile per warp, warp-unique B; fp16 m16n8k16
        const int wn = wid;   // 0..7

        float acc[4][4][4];
#pragma unroll
        for (int mt = 0; mt < 4; mt++)
#pragma unroll
            for (int nt = 0; nt < 4; nt++)
#pragma unroll
                for (int i = 0; i < 4; i++) acc[mt][nt][i] = 0.0f;

        int cs = 0, cph = 0;
#pragma unroll 1
        for (int c = 0; c < NCHUNK; c++) {
            MBAR_WAIT(sb + OFF_MB + cs * 8, cph);          // full[cs]
            uint32_t aB = sb + OFF_SA + cs * A_STAGE;
            uint32_t bB = sb + OFF_SB + cs * B_STAGE;
#pragma unroll
            for (int kh = 0; kh < 2; kh++) {
                // ---- B fragments: lds64 fp32 pair + cvt to f16x2 ----
                uint32_t bfr[4][2];
#pragma unroll
                for (int nt = 0; nt < 4; nt++) {
                    int s = wn * 32 + nt * 8 + l4;
                    uint32_t addr = bB + (uint32_t)((s * B_ROW_W + kh * 16 + 2 * kl) * 4);
                    float w[2], v[2];
                    lds64f(addr, w);            // k = 2kl, 2kl+1
                    lds64f(addr + 32, v);       // k = 2kl+8, 2kl+9
                    bfr[nt][0] = pack_f16x2(w[0], w[1]);
                    bfr[nt][1] = pack_f16x2(v[0], v[1]);
                }
                // ---- A fragments ----
                uint32_t afr[4][4];
#pragma unroll
                for (int mt = 0; mt < 4; mt++)
                    lds128(aB + (uint32_t)(((kh * 4 + mt) * 32 + lane) * 16), afr[mt]);
                // ---- 16-MMA burst ----
#pragma unroll
                for (int mt = 0; mt < 4; mt++)
#pragma unroll
                    for (int nt = 0; nt < 4; nt++)
                        mma_fp16(acc[mt][nt], afr[mt], bfr[nt]);
            }
            MBAR_ARRIVE(sb + OFF_MB + 24 + cs * 8);        // empty[cs]
            if (++cs == STAGES) { cs = 0; cph ^= 1; }
        }

        // ---- epilogue: un-scale by 2^-32 ----
#pragma unroll
        for (int mt = 0; mt < 4; mt++) {
            int row0 = bBase + mt * 16 + l4;
#pragma unroll
            for (int nt = 0; nt < 4; nt++) {
                int col = wn * 32 + nt * 8 + 2 * kl;
                *(float2*)(out + (size_t)row0 * SDIM + col) =
                    make_float2(acc[mt][nt][0] * INV_SCALE_F, acc[mt][nt][1] * INV_SCALE_F);
                *(float2*)(out + (size_t)(row0 + 8) * SDIM + col) =
                    make_float2(acc[mt][nt][2] * INV_SCALE_F, acc[mt][nt][3] * INV_SCALE_F);
            }
        }
    }
}

extern "C" void kernel_launch(void* const* d_in, const int* in_sizes, int n_in,
                              void* d_out, int out_size) {
    const float* ab   = (const float*)d_in[1];
    const float* temp = (const float*)d_in[2];
    const float* cr   = (const float*)d_in[3];
    const float* fuv  = (const float*)d_in[4];
    const float* inc  = (const float*)d_in[5];
    const float* alp  = (const float*)d_in[6];
    const float* bet  = (const float*)d_in[7];
    const float* gam  = (const float*)d_in[8];
    const int2*  rm   = (const int2*)d_in[9];
    const int*   rty  = (const int*)d_in[10];
    float* out = (float*)d_out;

    cudaFuncSetAttribute(fused_mma, cudaFuncAttributeMaxDynamicSharedMemorySize, SMEM_BYTES);
    fused_mma<<<BDIM / BM, THREADS, SMEM_BYTES>>>(ab, temp, cr, fuv, inc, alp, bet, gam,
                                                  rm, rty, out);
}